// round 7
// baseline (speedup 1.0000x reference)
#include <cuda_runtime.h>
#include <math.h>

// Global scratch (no allocations allowed):
// g_acc[0]=count_valid, [1]=count_in_bins, [2]=A0, [3]=B0, [4]=A1, [5]=B1, [6]=sum_exp
__device__ double g_acc[7];
__device__ unsigned int g_done;

__global__ void ghm_init_kernel() {
    if (threadIdx.x < 7) g_acc[threadIdx.x] = 0.0;
    if (threadIdx.x == 0) g_done = 0u;
}

__device__ __forceinline__ float warp_sum(float v) {
    #pragma unroll
    for (int off = 16; off; off >>= 1)
        v += __shfl_down_sync(0xffffffffu, v, off);
    return v;
}

__global__ void __launch_bounds__(256)
ghm_main_kernel(const float4* __restrict__ pred4,
                const float4* __restrict__ target4,
                float* __restrict__ out,
                int n4, int n_total) {
    float cv = 0.f, cb = 0.f, a0 = 0.f, b0 = 0.f, a1 = 0.f, b1 = 0.f, es = 0.f;

    const int stride = gridDim.x * blockDim.x;
    const int gid = blockIdx.x * blockDim.x + threadIdx.x;

    for (int i = gid; i < n4; i += stride) {
        float4 p4 = __ldg(pred4 + i);
        float4 t4 = __ldg(target4 + i);

        float ps[4] = {p4.x, p4.y, p4.z, p4.w};
        float ts[4] = {t4.x, t4.y, t4.z, t4.w};

        #pragma unroll
        for (int k = 0; k < 4; k++) {
            float p = ps[k];
            float t = ts[k];
            float e = __expf(p);                      // reused for sigmoid AND LSE
            float sig = __fdividef(e, 1.0f + e);      // sigmoid(p)
            float g = fabsf(sig - t);
            bool valid = isfinite(g) && isfinite(t);
            if (valid) {
                cv += 1.0f;
                // searchsorted-left index <= BINS  <=>  g <= last edge (1 + 1e-6)
                if (g <= 1.000001f) cb += 1.0f;
                float tp = t * p;
                if (t > p) { a0 += t; a1 += tp; }
                else       { b0 += t; b1 += tp; }
            }
            es += e;                                  // logsumexp over ALL pred
        }
    }

    // Scalar tail (N not divisible by 4) — handled by global thread 0 only.
    if (gid == 0) {
        const float* pred = (const float*)pred4;
        const float* target = (const float*)target4;
        for (int i = n4 * 4; i < n_total; i++) {
            float p = pred[i];
            float t = target[i];
            float e = __expf(p);
            float sig = __fdividef(e, 1.0f + e);
            float g = fabsf(sig - t);
            bool valid = isfinite(g) && isfinite(t);
            if (valid) {
                cv += 1.0f;
                if (g <= 1.000001f) cb += 1.0f;
                float tp = t * p;
                if (t > p) { a0 += t; a1 += tp; }
                else       { b0 += t; b1 += tp; }
            }
            es += e;
        }
    }

    // Warp reduce (float), then block reduce (double), then global atomics.
    cv = warp_sum(cv); cb = warp_sum(cb);
    a0 = warp_sum(a0); b0 = warp_sum(b0);
    a1 = warp_sum(a1); b1 = warp_sum(b1);
    es = warp_sum(es);

    __shared__ double sh[8][7];
    const int warp = threadIdx.x >> 5;
    const int lane = threadIdx.x & 31;
    if (lane == 0) {
        sh[warp][0] = (double)cv; sh[warp][1] = (double)cb;
        sh[warp][2] = (double)a0; sh[warp][3] = (double)b0;
        sh[warp][4] = (double)a1; sh[warp][5] = (double)b1;
        sh[warp][6] = (double)es;
    }
    __syncthreads();

    if (threadIdx.x == 0) {
        const int nw = (blockDim.x + 31) >> 5;
        double acc[7] = {0, 0, 0, 0, 0, 0, 0};
        for (int w = 0; w < nw; w++)
            #pragma unroll
            for (int j = 0; j < 7; j++) acc[j] += sh[w][j];
        #pragma unroll
        for (int j = 0; j < 7; j++) atomicAdd(&g_acc[j], acc[j]);

        __threadfence();
        unsigned ticket = atomicAdd(&g_done, 1u);
        if (ticket == gridDim.x - 1) {
            // Last block: all other blocks' atomics to g_acc are visible.
            double r[7];
            #pragma unroll
            for (int j = 0; j < 7; j++) r[j] = atomicAdd(&g_acc[j], 0.0);

            double total_samples = r[0];
            double tp_raw = 0.5 * r[1];              // (1-momentum) * sum(counts)
            double total_negatives = total_samples - tp_raw;   // pre-clamp
            double total_positives = tp_raw < 1.0 ? 1.0 : tp_raw;
            double ratio = total_negatives / total_positives;
            double lse = log(r[6]);
            double sum_wt  = ratio * r[2] + r[3];    // sum(w * t)
            double sum_wtp = ratio * r[4] + r[5];    // sum(w * t * pred)
            out[0] = (float)(-sum_wtp + lse * sum_wt);
        }
    }
}

extern "C" void kernel_launch(void* const* d_in, const int* in_sizes, int n_in,
                              void* d_out, int out_size) {
    const float* pred   = (const float*)d_in[0];
    const float* target = (const float*)d_in[1];
    float* out = (float*)d_out;
    int n = in_sizes[0];
    int n4 = n >> 2;

    const int threads = 256;
    const int blocks = 1184;  // 148 SMs * 8 blocks

    ghm_init_kernel<<<1, 32>>>();
    ghm_main_kernel<<<blocks, threads>>>((const float4*)pred,
                                         (const float4*)target,
                                         out, n4, n);
}

// round 8
// speedup vs baseline: 1.1886x; 1.1886x over previous
#include <cuda_runtime.h>
#include <math.h>

// Global scratch (no allocations allowed):
// g_acc: [0]=count_valid, [1]=count_in_bins, [2]=sum_t(t>p), [3]=sum_tp(t>p),
//        [4]=sum_t(all valid), [5]=sum_tp(all valid), [6]=sum_exp
__device__ double g_acc[7];
__device__ unsigned int g_done;

__global__ void ghm_init_kernel() {
    if (threadIdx.x < 7) g_acc[threadIdx.x] = 0.0;
    if (threadIdx.x == 0) g_done = 0u;
}

__device__ __forceinline__ float warp_sum(float v) {
    #pragma unroll
    for (int off = 16; off; off >>= 1)
        v += __shfl_down_sync(0xffffffffu, v, off);
    return v;
}

// One element. No division: g = |e - t - t*e| / (1+e); compare scaled by (1+e)>0.
// valid <=> num finite && t finite (matches old g-finite semantics).
__device__ __forceinline__ void ghm_elem(float p, float t,
                                         float& cv, float& cb,
                                         float& a0, float& a1,
                                         float& s0, float& s1, float& es) {
    float e   = __expf(p);
    float num = fmaf(-t, e, e - t);          // e - t - t*e
    float den = 1.0f + e;
    bool valid = isfinite(num) && isfinite(t);
    float tp = t * p;
    if (valid) {
        cv += 1.0f;
        if (fabsf(num) <= 1.000001f * den) cb += 1.0f;   // g <= last edge
        s0 += t;  s1 += tp;
        if (t > p) { a0 += t; a1 += tp; }
    }
    es += e;                                  // logsumexp over ALL pred
}

__global__ void __launch_bounds__(256, 4)
ghm_main_kernel(const float4* __restrict__ pred4,
                const float4* __restrict__ target4,
                float* __restrict__ out,
                int n4, int n_total) {
    float cv = 0.f, cb = 0.f, a0 = 0.f, a1 = 0.f, s0 = 0.f, s1 = 0.f, es = 0.f;

    const int stride  = gridDim.x * blockDim.x;
    const int gid     = blockIdx.x * blockDim.x + threadIdx.x;
    const int stride4 = stride * 4;

    int i = gid;
    // Main loop: 8 front-batched independent LDG.128 per iteration (MLP_p1 = 8).
    for (; i + 3 * stride < n4; i += stride4) {
        float4 p[4], t[4];
        #pragma unroll
        for (int j = 0; j < 4; j++) p[j] = __ldg(pred4 + i + j * stride);
        #pragma unroll
        for (int j = 0; j < 4; j++) t[j] = __ldg(target4 + i + j * stride);

        #pragma unroll
        for (int j = 0; j < 4; j++) {
            ghm_elem(p[j].x, t[j].x, cv, cb, a0, a1, s0, s1, es);
            ghm_elem(p[j].y, t[j].y, cv, cb, a0, a1, s0, s1, es);
            ghm_elem(p[j].z, t[j].z, cv, cb, a0, a1, s0, s1, es);
            ghm_elem(p[j].w, t[j].w, cv, cb, a0, a1, s0, s1, es);
        }
    }
    // Remainder float4s
    for (; i < n4; i += stride) {
        float4 p = __ldg(pred4 + i);
        float4 t = __ldg(target4 + i);
        ghm_elem(p.x, t.x, cv, cb, a0, a1, s0, s1, es);
        ghm_elem(p.y, t.y, cv, cb, a0, a1, s0, s1, es);
        ghm_elem(p.z, t.z, cv, cb, a0, a1, s0, s1, es);
        ghm_elem(p.w, t.w, cv, cb, a0, a1, s0, s1, es);
    }
    // Scalar tail (N % 4) — thread 0 only.
    if (gid == 0) {
        const float* pred   = (const float*)pred4;
        const float* target = (const float*)target4;
        for (int k = n4 * 4; k < n_total; k++)
            ghm_elem(pred[k], target[k], cv, cb, a0, a1, s0, s1, es);
    }

    // Warp reduce (float), block reduce (double), then global atomics.
    cv = warp_sum(cv); cb = warp_sum(cb);
    a0 = warp_sum(a0); a1 = warp_sum(a1);
    s0 = warp_sum(s0); s1 = warp_sum(s1);
    es = warp_sum(es);

    __shared__ double sh[8][7];
    const int warp = threadIdx.x >> 5;
    const int lane = threadIdx.x & 31;
    if (lane == 0) {
        sh[warp][0] = (double)cv; sh[warp][1] = (double)cb;
        sh[warp][2] = (double)a0; sh[warp][3] = (double)a1;
        sh[warp][4] = (double)s0; sh[warp][5] = (double)s1;
        sh[warp][6] = (double)es;
    }
    __syncthreads();

    if (threadIdx.x == 0) {
        const int nw = (blockDim.x + 31) >> 5;
        double acc[7] = {0, 0, 0, 0, 0, 0, 0};
        for (int w = 0; w < nw; w++)
            #pragma unroll
            for (int j = 0; j < 7; j++) acc[j] += sh[w][j];
        #pragma unroll
        for (int j = 0; j < 7; j++) atomicAdd(&g_acc[j], acc[j]);

        __threadfence();
        unsigned ticket = atomicAdd(&g_done, 1u);
        if (ticket == gridDim.x - 1) {
            double r[7];
            #pragma unroll
            for (int j = 0; j < 7; j++) r[j] = atomicAdd(&g_acc[j], 0.0);

            double total_samples   = r[0];
            double tp_raw          = 0.5 * r[1];               // (1-momentum)*sum(counts)
            double total_negatives = total_samples - tp_raw;   // pre-clamp
            double total_positives = tp_raw < 1.0 ? 1.0 : tp_raw;
            double ratio = total_negatives / total_positives;
            double lse   = log(r[6]);
            // A-part: t>p bucket gets weight=ratio; rest weight=1.
            double sum_wt  = ratio * r[2] + (r[4] - r[2]);     // sum(w*t)
            double sum_wtp = ratio * r[3] + (r[5] - r[3]);     // sum(w*t*pred)
            out[0] = (float)(-sum_wtp + lse * sum_wt);
        }
    }
}

extern "C" void kernel_launch(void* const* d_in, const int* in_sizes, int n_in,
                              void* d_out, int out_size) {
    const float* pred   = (const float*)d_in[0];
    const float* target = (const float*)d_in[1];
    float* out = (float*)d_out;
    int n  = in_sizes[0];
    int n4 = n >> 2;

    const int threads = 256;
    const int blocks  = 592;   // 148 SMs * 4 blocks = exactly one resident wave (32 warps/SM)

    ghm_init_kernel<<<1, 32>>>();
    ghm_main_kernel<<<blocks, threads>>>((const float4*)pred,
                                         (const float4*)target,
                                         out, n4, n);
}